// round 12
// baseline (speedup 1.0000x reference)
#include <cuda_runtime.h>
#include <math.h>

// Problem dimensions
#define Bc   2
#define Sc   1024
#define Dc   768
#define Hc   12
#define HDc  64
#define DFFc 3072
#define Mrows (Bc*Sc)          // 2048

// Packed f32x2 helpers (FFMA2 path — PTX-only)
#define FMA_F32X2(d, a, b, c) \
    asm("fma.rn.f32x2 %0, %1, %2, %3;" : "=l"(d) : "l"(a), "l"(b), "l"(c))
#define PACK2F(out, lo, hi) \
    asm("mov.b64 %0, {%1, %2};" : "=l"(out) : "f"(lo), "f"(hi))
#define UNPACK2F(lo, hi, in) \
    asm("mov.b64 {%0, %1}, %2;" : "=f"(lo), "=f"(hi) : "l"(in))

// ---------------------------------------------------------------------------
// Scratch (allocation-free: __device__ globals)
// ---------------------------------------------------------------------------
__device__ float g_xln [Mrows*Dc];
__device__ float g_qkv [Mrows*3*Dc];
__device__ float g_att [Mrows*Dc];
__device__ float g_res1[Mrows*Dc];
__device__ float g_hln [Mrows*Dc];
__device__ float g_ff  [Mrows*DFFc];

// ---------------------------------------------------------------------------
// LayerNorm: one block per row of 768
// ---------------------------------------------------------------------------
__global__ __launch_bounds__(256) void ln_kernel(
    const float* __restrict__ x, const float* __restrict__ g,
    const float* __restrict__ b, float* __restrict__ y)
{
    __shared__ float red[16];
    int row = blockIdx.x;
    int t = threadIdx.x;
    const float* xr = x + (size_t)row * Dc;
    float v0 = xr[t], v1 = xr[t + 256], v2 = xr[t + 512];
    float s  = v0 + v1 + v2;
    float ss = v0*v0 + v1*v1 + v2*v2;
    #pragma unroll
    for (int o = 16; o > 0; o >>= 1) {
        s  += __shfl_xor_sync(0xffffffffu, s,  o);
        ss += __shfl_xor_sync(0xffffffffu, ss, o);
    }
    int w = t >> 5;
    if ((t & 31) == 0) { red[w] = s; red[8 + w] = ss; }
    __syncthreads();
    s = 0.f; ss = 0.f;
    #pragma unroll
    for (int i = 0; i < 8; i++) { s += red[i]; ss += red[8 + i]; }
    float mean = s * (1.0f / Dc);
    float var  = ss * (1.0f / Dc) - mean * mean;
    float inv  = rsqrtf(var + 1e-5f);
    float* yr = y + (size_t)row * Dc;
    yr[t]       = (v0 - mean) * inv * g[t]       + b[t];
    yr[t + 256] = (v1 - mean) * inv * g[t + 256] + b[t + 256];
    yr[t + 512] = (v2 - mean) * inv * g[t + 512] + b[t + 512];
}

// ---------------------------------------------------------------------------
// SGEMM, packed-f32x2 inner product (FFMA2), 256 threads, 2 CTAs/SM:
// C[M,N] = A[M,K]*B[N,K]^T (+bias)(relu)(+res)
// BN=128, BK=16. BM template: 128 (8x8/thread) or 64 (4x8/thread).
// Smem double-buffered, one __syncthreads per BK.
// ---------------------------------------------------------------------------
template<int BM>
__global__ __launch_bounds__(256, 2) void sgemm2(
    const float* __restrict__ A, const float* __restrict__ B,
    const float* __restrict__ bias, const float* __restrict__ res,
    float* __restrict__ C, int M, int N, int K, int do_relu)
{
    constexpr int BN = 128;
    constexpr int BK = 16;
    constexpr int TM = BM / 16;          // 8 or 4
    constexpr int AV = BM / 64;          // float4s/thread for A tile (2 or 1)

    __shared__ float As[2][BK][BM];
    __shared__ float Bs[2][BK][BN];

    int tid = threadIdx.x;
    int tx = tid & 15, ty = tid >> 4;
    int bm = blockIdx.y * BM, bn = blockIdx.x * BN;

    int arow, akq;
    if (BM == 128) { arow = tid >> 1; akq = (tid & 1) * 8; }
    else           { arow = tid >> 2; akq = (tid & 3) * 4; }
    int brow = tid >> 1, bkq = (tid & 1) * 8;

    const float* Ag = A + (size_t)(bm + arow) * K + akq;
    const float* Bg = B + (size_t)(bn + brow) * K + bkq;

    float4 areg[AV], breg[2];

    unsigned long long acc[TM][4];
    #pragma unroll
    for (int i = 0; i < TM; i++)
        #pragma unroll
        for (int j = 0; j < 4; j++) acc[i][j] = 0ull;

    // prologue: tile 0
    #pragma unroll
    for (int v = 0; v < AV; v++) areg[v] = *(const float4*)(Ag + 4 * v);
    breg[0] = *(const float4*)(Bg);
    breg[1] = *(const float4*)(Bg + 4);

    #pragma unroll
    for (int v = 0; v < AV; v++) {
        As[0][akq + 4*v + 0][arow] = (&areg[v].x)[0];
        As[0][akq + 4*v + 1][arow] = (&areg[v].x)[1];
        As[0][akq + 4*v + 2][arow] = (&areg[v].x)[2];
        As[0][akq + 4*v + 3][arow] = (&areg[v].x)[3];
    }
    #pragma unroll
    for (int v = 0; v < 2; v++) {
        Bs[0][bkq + 4*v + 0][brow] = (&breg[v].x)[0];
        Bs[0][bkq + 4*v + 1][brow] = (&breg[v].x)[1];
        Bs[0][bkq + 4*v + 2][brow] = (&breg[v].x)[2];
        Bs[0][bkq + 4*v + 3][brow] = (&breg[v].x)[3];
    }
    __syncthreads();

    int nt = K / BK;
    for (int kt = 0; kt < nt; kt++) {
        int cur = kt & 1;
        if (kt + 1 < nt) {
            const float* Ag2 = Ag + (size_t)(kt + 1) * BK;
            const float* Bg2 = Bg + (size_t)(kt + 1) * BK;
            #pragma unroll
            for (int v = 0; v < AV; v++) areg[v] = *(const float4*)(Ag2 + 4 * v);
            breg[0] = *(const float4*)(Bg2);
            breg[1] = *(const float4*)(Bg2 + 4);
        }

        #pragma unroll
        for (int kk = 0; kk < BK; kk++) {
            // A fragment (TM floats), duplicated packs
            unsigned long long ap[TM], bp[4];
            if (BM == 128) {
                float4 a0 = *(const float4*)&As[cur][kk][4 * ty];
                float4 a1 = *(const float4*)&As[cur][kk][64 + 4 * ty];
                PACK2F(ap[0], a0.x, a0.x); PACK2F(ap[1], a0.y, a0.y);
                PACK2F(ap[2], a0.z, a0.z); PACK2F(ap[3], a0.w, a0.w);
                PACK2F(ap[4], a1.x, a1.x); PACK2F(ap[5], a1.y, a1.y);
                PACK2F(ap[6], a1.z, a1.z); PACK2F(ap[7], a1.w, a1.w);
            } else {
                float4 a0 = *(const float4*)&As[cur][kk][4 * ty];
                PACK2F(ap[0], a0.x, a0.x); PACK2F(ap[1], a0.y, a0.y);
                PACK2F(ap[2], a0.z, a0.z); PACK2F(ap[3], a0.w, a0.w);
            }
            float4 b0 = *(const float4*)&Bs[cur][kk][4 * tx];
            float4 b1 = *(const float4*)&Bs[cur][kk][64 + 4 * tx];
            PACK2F(bp[0], b0.x, b0.y); PACK2F(bp[1], b0.z, b0.w);
            PACK2F(bp[2], b1.x, b1.y); PACK2F(bp[3], b1.z, b1.w);

            #pragma unroll
            for (int i = 0; i < TM; i++)
                #pragma unroll
                for (int j = 0; j < 4; j++)
                    FMA_F32X2(acc[i][j], ap[i], bp[j], acc[i][j]);
        }

        if (kt + 1 < nt) {
            int nxt = cur ^ 1;
            #pragma unroll
            for (int v = 0; v < AV; v++) {
                As[nxt][akq + 4*v + 0][arow] = (&areg[v].x)[0];
                As[nxt][akq + 4*v + 1][arow] = (&areg[v].x)[1];
                As[nxt][akq + 4*v + 2][arow] = (&areg[v].x)[2];
                As[nxt][akq + 4*v + 3][arow] = (&areg[v].x)[3];
            }
            #pragma unroll
            for (int v = 0; v < 2; v++) {
                Bs[nxt][bkq + 4*v + 0][brow] = (&breg[v].x)[0];
                Bs[nxt][bkq + 4*v + 1][brow] = (&breg[v].x)[1];
                Bs[nxt][bkq + 4*v + 2][brow] = (&breg[v].x)[2];
                Bs[nxt][bkq + 4*v + 3][brow] = (&breg[v].x)[3];
            }
            __syncthreads();
        }
    }

    // Epilogue: unpack pairs, fuse bias/relu/residual, store float4s
    #pragma unroll
    for (int i = 0; i < TM; i++) {
        int r;
        if (BM == 128) r = bm + ((i < 4) ? (4 * ty + i) : (64 + 4 * ty + (i - 4)));
        else           r = bm + 4 * ty + i;
        float o[8];
        UNPACK2F(o[0], o[1], acc[i][0]);
        UNPACK2F(o[2], o[3], acc[i][1]);
        UNPACK2F(o[4], o[5], acc[i][2]);
        UNPACK2F(o[6], o[7], acc[i][3]);
        #pragma unroll
        for (int half = 0; half < 2; half++) {
            int c0 = bn + half * 64 + 4 * tx;
            float4 v;
            v.x = o[half * 4 + 0]; v.y = o[half * 4 + 1];
            v.z = o[half * 4 + 2]; v.w = o[half * 4 + 3];
            if (bias) {
                v.x += bias[c0 + 0]; v.y += bias[c0 + 1];
                v.z += bias[c0 + 2]; v.w += bias[c0 + 3];
            }
            if (do_relu) {
                v.x = fmaxf(v.x, 0.f); v.y = fmaxf(v.y, 0.f);
                v.z = fmaxf(v.z, 0.f); v.w = fmaxf(v.w, 0.f);
            }
            if (res) {
                float4 rv = *(const float4*)(res + (size_t)r * N + c0);
                v.x += rv.x; v.y += rv.y; v.z += rv.z; v.w += rv.w;
            }
            *(float4*)(C + (size_t)r * N + c0) = v;
        }
    }
}

// ---------------------------------------------------------------------------
// Fused attention (flash-style): per (q-block of 64, b*h)
// ---------------------------------------------------------------------------
#define ATT_SMEM_FLOATS (64*64 + 64*65 + 64*64 + 64*4)

__global__ __launch_bounds__(256) void attn_kernel(
    const float* __restrict__ qkv,          // [B,S,3D]
    const int* __restrict__ relm,           // [B,S,S]
    const unsigned char* __restrict__ mask, // [B,S] (bool)
    const float* __restrict__ relA,         // [3,64]
    float* __restrict__ out)                // [B,S,D]
{
    extern __shared__ float sm[];
    float* QS = sm;                 // 64*64
    float* KP = QS + 64 * 64;       // 64*65 (padded stride 65)
    float* VS = KP + 64 * 65;       // 64*64
    float* RR = VS + 64 * 64;       // 64*4

    int tid = threadIdx.x;
    int tx = tid & 15, ty = tid >> 4;
    int qb = blockIdx.x;            // 0..15
    int bh = blockIdx.y;            // 0..23
    int b = bh / Hc, h = bh % Hc;
    int q0 = qb * 64;

    const float* qbase = qkv + (size_t)(b * Sc) * (3 * Dc) + h * HDc;
    const float* kbase = qbase + Dc;
    const float* vbase = qbase + 2 * Dc;

    {
        int col4 = (tid & 15) * 4;
        for (int r = tid >> 4; r < 64; r += 16) {
            float4 v = *(const float4*)(qbase + (size_t)(q0 + r) * (3 * Dc) + col4);
            *(float4*)&QS[r * 64 + col4] = v;
        }
    }
    __syncthreads();

    if (tid < 192) {
        int q = tid / 3, c = tid % 3;
        float s = 0.f;
        const float* arow = relA + c * HDc;
        #pragma unroll 8
        for (int d = 0; d < 64; d++) s += QS[q * 64 + d] * arow[d];
        RR[q * 4 + c] = s;
    }
    __syncthreads();

    float mrow[4], lrow[4], o[4][4];
    #pragma unroll
    for (int i = 0; i < 4; i++) {
        mrow[i] = -INFINITY; lrow[i] = 0.f;
        #pragma unroll
        for (int j = 0; j < 4; j++) o[i][j] = 0.f;
    }

    const int* rmrow = relm + ((size_t)b * Sc + q0) * Sc;
    const unsigned char* mkrow = mask + (size_t)b * Sc;

    for (int kb = 0; kb < Sc / 64; kb++) {
        int k0 = kb * 64;
        __syncthreads();
        {
            int col4 = (tid & 15) * 4;
            for (int r = tid >> 4; r < 64; r += 16) {
                float4 kv = *(const float4*)(kbase + (size_t)(k0 + r) * (3 * Dc) + col4);
                KP[r * 65 + col4 + 0] = kv.x; KP[r * 65 + col4 + 1] = kv.y;
                KP[r * 65 + col4 + 2] = kv.z; KP[r * 65 + col4 + 3] = kv.w;
                float4 vv = *(const float4*)(vbase + (size_t)(k0 + r) * (3 * Dc) + col4);
                *(float4*)&VS[r * 64 + col4] = vv;
            }
        }
        __syncthreads();

        float s[4][4];
        #pragma unroll
        for (int i = 0; i < 4; i++)
            #pragma unroll
            for (int j = 0; j < 4; j++) s[i][j] = 0.f;
        #pragma unroll 4
        for (int d = 0; d < 64; d++) {
            float a0 = QS[(4 * ty + 0) * 64 + d];
            float a1 = QS[(4 * ty + 1) * 64 + d];
            float a2 = QS[(4 * ty + 2) * 64 + d];
            float a3 = QS[(4 * ty + 3) * 64 + d];
            float b0 = KP[(4 * tx + 0) * 65 + d];
            float b1 = KP[(4 * tx + 1) * 65 + d];
            float b2 = KP[(4 * tx + 2) * 65 + d];
            float b3 = KP[(4 * tx + 3) * 65 + d];
            s[0][0] = fmaf(a0, b0, s[0][0]); s[0][1] = fmaf(a0, b1, s[0][1]);
            s[0][2] = fmaf(a0, b2, s[0][2]); s[0][3] = fmaf(a0, b3, s[0][3]);
            s[1][0] = fmaf(a1, b0, s[1][0]); s[1][1] = fmaf(a1, b1, s[1][1]);
            s[1][2] = fmaf(a1, b2, s[1][2]); s[1][3] = fmaf(a1, b3, s[1][3]);
            s[2][0] = fmaf(a2, b0, s[2][0]); s[2][1] = fmaf(a2, b1, s[2][1]);
            s[2][2] = fmaf(a2, b2, s[2][2]); s[2][3] = fmaf(a2, b3, s[2][3]);
            s[3][0] = fmaf(a3, b0, s[3][0]); s[3][1] = fmaf(a3, b1, s[3][1]);
            s[3][2] = fmaf(a3, b2, s[3][2]); s[3][3] = fmaf(a3, b3, s[3][3]);
        }

        #pragma unroll
        for (int j = 0; j < 4; j++) {
            int kg = k0 + 4 * tx + j;
            unsigned char mk = mkrow[kg];
            #pragma unroll
            for (int i = 0; i < 4; i++) {
                int ql = 4 * ty + i;
                int idx = rmrow[(size_t)ql * Sc + kg] + 1;   // 0,1,2
                float val = (s[i][j] + RR[ql * 4 + idx]) * 0.125f;
                s[i][j] = mk ? -INFINITY : val;
            }
        }

        #pragma unroll
        for (int i = 0; i < 4; i++) {
            float tm = fmaxf(fmaxf(s[i][0], s[i][1]), fmaxf(s[i][2], s[i][3]));
            #pragma unroll
            for (int off = 1; off < 16; off <<= 1)
                tm = fmaxf(tm, __shfl_xor_sync(0xffffffffu, tm, off));
            float nm = fmaxf(mrow[i], tm);
            if (nm == -INFINITY) continue;
            float alpha = (mrow[i] == -INFINITY) ? 0.f : __expf(mrow[i] - nm);
            float rs = 0.f;
            #pragma unroll
            for (int j = 0; j < 4; j++) {
                s[i][j] = __expf(s[i][j] - nm);
                rs += s[i][j];
            }
            #pragma unroll
            for (int off = 1; off < 16; off <<= 1)
                rs += __shfl_xor_sync(0xffffffffu, rs, off);
            lrow[i] = lrow[i] * alpha + rs;
            #pragma unroll
            for (int j = 0; j < 4; j++) o[i][j] *= alpha;
            mrow[i] = nm;
        }

        __syncthreads();
        #pragma unroll
        for (int i = 0; i < 4; i++)
            #pragma unroll
            for (int j = 0; j < 4; j++)
                KP[(4 * ty + i) * 65 + 4 * tx + j] = (mrow[i] == -INFINITY) ? 0.f : s[i][j];
        __syncthreads();

        #pragma unroll 4
        for (int k = 0; k < 64; k++) {
            float4 vv = *(const float4*)&VS[k * 64 + 4 * tx];
            float p0 = KP[(4 * ty + 0) * 65 + k];
            float p1 = KP[(4 * ty + 1) * 65 + k];
            float p2 = KP[(4 * ty + 2) * 65 + k];
            float p3 = KP[(4 * ty + 3) * 65 + k];
            o[0][0] = fmaf(p0, vv.x, o[0][0]); o[0][1] = fmaf(p0, vv.y, o[0][1]);
            o[0][2] = fmaf(p0, vv.z, o[0][2]); o[0][3] = fmaf(p0, vv.w, o[0][3]);
            o[1][0] = fmaf(p1, vv.x, o[1][0]); o[1][1] = fmaf(p1, vv.y, o[1][1]);
            o[1][2] = fmaf(p1, vv.z, o[1][2]); o[1][3] = fmaf(p1, vv.w, o[1][3]);
            o[2][0] = fmaf(p2, vv.x, o[2][0]); o[2][1] = fmaf(p2, vv.y, o[2][1]);
            o[2][2] = fmaf(p2, vv.z, o[2][2]); o[2][3] = fmaf(p2, vv.w, o[2][3]);
            o[3][0] = fmaf(p3, vv.x, o[3][0]); o[3][1] = fmaf(p3, vv.y, o[3][1]);
            o[3][2] = fmaf(p3, vv.z, o[3][2]); o[3][3] = fmaf(p3, vv.w, o[3][3]);
        }
    }

    #pragma unroll
    for (int i = 0; i < 4; i++) {
        float inv = (lrow[i] > 0.f) ? (1.f / lrow[i]) : 0.f;
        int qg = q0 + 4 * ty + i;
        float4 v;
        v.x = o[i][0] * inv; v.y = o[i][1] * inv;
        v.z = o[i][2] * inv; v.w = o[i][3] * inv;
        *(float4*)(out + ((size_t)(b * Sc) + qg) * Dc + h * HDc + 4 * tx) = v;
    }
}

// ---------------------------------------------------------------------------
// Launcher
// ---------------------------------------------------------------------------
extern "C" void kernel_launch(void* const* d_in, const int* in_sizes, int n_in,
                              void* d_out, int out_size)
{
    const float*         inp   = (const float*)d_in[0];
    const unsigned char* mask  = (const unsigned char*)d_in[1];
    const int*           relm  = (const int*)d_in[2];
    const float*         qkv_w = (const float*)d_in[3];
    const float*         relA  = (const float*)d_in[4];
    const float*         o_w   = (const float*)d_in[5];
    const float*         w1    = (const float*)d_in[6];
    const float*         b1    = (const float*)d_in[7];
    const float*         w2    = (const float*)d_in[8];
    const float*         b2    = (const float*)d_in[9];
    const float*         ln1g  = (const float*)d_in[10];
    const float*         ln1b  = (const float*)d_in[11];
    const float*         ln2g  = (const float*)d_in[12];
    const float*         ln2b  = (const float*)d_in[13];
    float* out = (float*)d_out;

    float *p_xln, *p_qkv, *p_att, *p_res1, *p_hln, *p_ff;
    cudaGetSymbolAddress((void**)&p_xln,  g_xln);
    cudaGetSymbolAddress((void**)&p_qkv,  g_qkv);
    cudaGetSymbolAddress((void**)&p_att,  g_att);
    cudaGetSymbolAddress((void**)&p_res1, g_res1);
    cudaGetSymbolAddress((void**)&p_hln,  g_hln);
    cudaGetSymbolAddress((void**)&p_ff,   g_ff);

    cudaFuncSetAttribute(attn_kernel, cudaFuncAttributeMaxDynamicSharedMemorySize,
                         ATT_SMEM_FLOATS * (int)sizeof(float));

    // 1. LN1
    ln_kernel<<<Mrows, 256>>>(inp, ln1g, ln1b, p_xln);

    // 2. QKV = xln @ qkv_w^T       [2048 x 2304], BM=128, grid 18x16=288
    sgemm2<128><<<dim3(3 * Dc / 128, Mrows / 128), 256>>>(
        p_xln, qkv_w, nullptr, nullptr, p_qkv, Mrows, 3 * Dc, Dc, 0);

    // 3. Fused attention
    attn_kernel<<<dim3(Sc / 64, Bc * Hc), 256, ATT_SMEM_FLOATS * sizeof(float)>>>(
        p_qkv, relm, mask, relA, p_att);

    // 4. res1 = inp + att @ o_w^T  [2048 x 768], BM=64, grid 6x32=192
    sgemm2<64><<<dim3(Dc / 128, Mrows / 64), 256>>>(
        p_att, o_w, nullptr, inp, p_res1, Mrows, Dc, Dc, 0);

    // 5. LN2
    ln_kernel<<<Mrows, 256>>>(p_res1, ln2g, ln2b, p_hln);

    // 6. ff = relu(hln @ w1^T + b1)  [2048 x 3072], BM=128, grid 24x16=384
    sgemm2<128><<<dim3(DFFc / 128, Mrows / 128), 256>>>(
        p_hln, w1, b1, nullptr, p_ff, Mrows, DFFc, Dc, 1);

    // 7. out = res1 + ff @ w2^T + b2  [2048 x 768], BM=64, grid 6x32=192
    sgemm2<64><<<dim3(Dc / 128, Mrows / 64), 256>>>(
        p_ff, w2, b2, p_res1, out, Mrows, Dc, DFFc, 0);
}

// round 13
// speedup vs baseline: 1.4208x; 1.4208x over previous
#include <cuda_runtime.h>
#include <math.h>

// Problem dimensions
#define Bc   2
#define Sc   1024
#define Dc   768
#define Hc   12
#define HDc  64
#define DFFc 3072
#define Mrows (Bc*Sc)          // 2048

// Packed f32x2 helpers (FFMA2 path — PTX-only)
#define FMA_F32X2(d, a, b, c) \
    asm("fma.rn.f32x2 %0, %1, %2, %3;" : "=l"(d) : "l"(a), "l"(b), "l"(c))
#define PACK2F(out, lo, hi) \
    asm("mov.b64 %0, {%1, %2};" : "=l"(out) : "f"(lo), "f"(hi))
#define UNPACK2F(lo, hi, in) \
    asm("mov.b64 {%0, %1}, %2;" : "=f"(lo), "=f"(hi) : "l"(in))

// ---------------------------------------------------------------------------
// Scratch (allocation-free: __device__ globals)
// ---------------------------------------------------------------------------
__device__ float g_xln [Mrows*Dc];
__device__ float g_qkv [Mrows*3*Dc];
__device__ float g_att [Mrows*Dc];
__device__ float g_res1[Mrows*Dc];
__device__ float g_hln [Mrows*Dc];
__device__ float g_ff  [Mrows*DFFc];

// ---------------------------------------------------------------------------
// LayerNorm: one block per row of 768
// ---------------------------------------------------------------------------
__global__ __launch_bounds__(256) void ln_kernel(
    const float* __restrict__ x, const float* __restrict__ g,
    const float* __restrict__ b, float* __restrict__ y)
{
    __shared__ float red[16];
    int row = blockIdx.x;
    int t = threadIdx.x;
    const float* xr = x + (size_t)row * Dc;
    float v0 = xr[t], v1 = xr[t + 256], v2 = xr[t + 512];
    float s  = v0 + v1 + v2;
    float ss = v0*v0 + v1*v1 + v2*v2;
    #pragma unroll
    for (int o = 16; o > 0; o >>= 1) {
        s  += __shfl_xor_sync(0xffffffffu, s,  o);
        ss += __shfl_xor_sync(0xffffffffu, ss, o);
    }
    int w = t >> 5;
    if ((t & 31) == 0) { red[w] = s; red[8 + w] = ss; }
    __syncthreads();
    s = 0.f; ss = 0.f;
    #pragma unroll
    for (int i = 0; i < 8; i++) { s += red[i]; ss += red[8 + i]; }
    float mean = s * (1.0f / Dc);
    float var  = ss * (1.0f / Dc) - mean * mean;
    float inv  = rsqrtf(var + 1e-5f);
    float* yr = y + (size_t)row * Dc;
    yr[t]       = (v0 - mean) * inv * g[t]       + b[t];
    yr[t + 256] = (v1 - mean) * inv * g[t + 256] + b[t + 256];
    yr[t + 512] = (v2 - mean) * inv * g[t + 512] + b[t + 512];
}

// ---------------------------------------------------------------------------
// SGEMM A (R10 engine): tile 64x128, BK=16, 128 threads, 8x8/thread, FFMA2.
// For wide-N GEMMs (QKV: 576 CTAs, MLP1: 768 CTAs).
// ---------------------------------------------------------------------------
__global__ __launch_bounds__(128, 4) void sgemm_x2(
    const float* __restrict__ A, const float* __restrict__ B,
    const float* __restrict__ bias, const float* __restrict__ res,
    float* __restrict__ C, int M, int N, int K, int do_relu)
{
    constexpr int BK = 16;

    __shared__ float As[2][BK][64];
    __shared__ float Bs[2][BK][128];

    int tid = threadIdx.x;
    int tx = tid & 15;          // 0..15 -> column groups
    int ty = tid >> 4;          // 0..7  -> row groups (8 rows each)
    int bm = blockIdx.y * 64, bn = blockIdx.x * 128;

    int arow = tid >> 1;             // 0..63
    int akq  = (tid & 1) * 8;        // 0 or 8
    const float* Ag = A + (size_t)(bm + arow) * K + akq;
    const float* Bg = B + (size_t)(bn + tid) * K;    // each thread one B row, 16 k

    float4 areg[2], breg[4];

    unsigned long long acc[8][4];
    #pragma unroll
    for (int i = 0; i < 8; i++)
        #pragma unroll
        for (int j = 0; j < 4; j++) acc[i][j] = 0ull;

    areg[0] = *(const float4*)(Ag);
    areg[1] = *(const float4*)(Ag + 4);
    #pragma unroll
    for (int v = 0; v < 4; v++) breg[v] = *(const float4*)(Bg + 4 * v);

    #pragma unroll
    for (int v = 0; v < 2; v++) {
        As[0][akq + 4*v + 0][arow] = (&areg[v].x)[0];
        As[0][akq + 4*v + 1][arow] = (&areg[v].x)[1];
        As[0][akq + 4*v + 2][arow] = (&areg[v].x)[2];
        As[0][akq + 4*v + 3][arow] = (&areg[v].x)[3];
    }
    #pragma unroll
    for (int v = 0; v < 4; v++) {
        Bs[0][4*v + 0][tid] = breg[v].x;
        Bs[0][4*v + 1][tid] = breg[v].y;
        Bs[0][4*v + 2][tid] = breg[v].z;
        Bs[0][4*v + 3][tid] = breg[v].w;
    }
    __syncthreads();

    int nt = K / BK;
    for (int kt = 0; kt < nt; kt++) {
        int cur = kt & 1;
        if (kt + 1 < nt) {
            const float* Ag2 = Ag + (size_t)(kt + 1) * BK;
            const float* Bg2 = Bg + (size_t)(kt + 1) * BK;
            areg[0] = *(const float4*)(Ag2);
            areg[1] = *(const float4*)(Ag2 + 4);
            #pragma unroll
            for (int v = 0; v < 4; v++) breg[v] = *(const float4*)(Bg2 + 4 * v);
        }

        #pragma unroll
        for (int kk = 0; kk < BK; kk++) {
            float4 a0 = *(const float4*)&As[cur][kk][8 * ty];
            float4 a1 = *(const float4*)&As[cur][kk][8 * ty + 4];
            float4 b0 = *(const float4*)&Bs[cur][kk][4 * tx];
            float4 b1 = *(const float4*)&Bs[cur][kk][64 + 4 * tx];

            unsigned long long ap[8], bp[4];
            PACK2F(ap[0], a0.x, a0.x); PACK2F(ap[1], a0.y, a0.y);
            PACK2F(ap[2], a0.z, a0.z); PACK2F(ap[3], a0.w, a0.w);
            PACK2F(ap[4], a1.x, a1.x); PACK2F(ap[5], a1.y, a1.y);
            PACK2F(ap[6], a1.z, a1.z); PACK2F(ap[7], a1.w, a1.w);
            PACK2F(bp[0], b0.x, b0.y); PACK2F(bp[1], b0.z, b0.w);
            PACK2F(bp[2], b1.x, b1.y); PACK2F(bp[3], b1.z, b1.w);

            #pragma unroll
            for (int i = 0; i < 8; i++)
                #pragma unroll
                for (int j = 0; j < 4; j++)
                    FMA_F32X2(acc[i][j], ap[i], bp[j], acc[i][j]);
        }

        if (kt + 1 < nt) {
            int nxt = cur ^ 1;
            #pragma unroll
            for (int v = 0; v < 2; v++) {
                As[nxt][akq + 4*v + 0][arow] = (&areg[v].x)[0];
                As[nxt][akq + 4*v + 1][arow] = (&areg[v].x)[1];
                As[nxt][akq + 4*v + 2][arow] = (&areg[v].x)[2];
                As[nxt][akq + 4*v + 3][arow] = (&areg[v].x)[3];
            }
            #pragma unroll
            for (int v = 0; v < 4; v++) {
                Bs[nxt][4*v + 0][tid] = breg[v].x;
                Bs[nxt][4*v + 1][tid] = breg[v].y;
                Bs[nxt][4*v + 2][tid] = breg[v].z;
                Bs[nxt][4*v + 3][tid] = breg[v].w;
            }
            __syncthreads();
        }
    }

    #pragma unroll
    for (int i = 0; i < 8; i++) {
        int r = bm + 8 * ty + i;
        float o[8];
        UNPACK2F(o[0], o[1], acc[i][0]);
        UNPACK2F(o[2], o[3], acc[i][1]);
        UNPACK2F(o[4], o[5], acc[i][2]);
        UNPACK2F(o[6], o[7], acc[i][3]);
        #pragma unroll
        for (int half = 0; half < 2; half++) {
            int c0 = bn + half * 64 + 4 * tx;
            float4 v;
            v.x = o[half * 4 + 0]; v.y = o[half * 4 + 1];
            v.z = o[half * 4 + 2]; v.w = o[half * 4 + 3];
            if (bias) {
                v.x += bias[c0 + 0]; v.y += bias[c0 + 1];
                v.z += bias[c0 + 2]; v.w += bias[c0 + 3];
            }
            if (do_relu) {
                v.x = fmaxf(v.x, 0.f); v.y = fmaxf(v.y, 0.f);
                v.z = fmaxf(v.z, 0.f); v.w = fmaxf(v.w, 0.f);
            }
            if (res) {
                float4 rv = *(const float4*)(res + (size_t)r * N + c0);
                v.x += rv.x; v.y += rv.y; v.z += rv.z; v.w += rv.w;
            }
            *(float4*)(C + (size_t)r * N + c0) = v;
        }
    }
}

// ---------------------------------------------------------------------------
// SGEMM B: tile 64x64, BK=16, 128 threads, 4x8/thread, FFMA2.
// For N=768 GEMMs (O-proj, MLP2): grid 12x32=384 CTAs -> better SM fill.
// ---------------------------------------------------------------------------
__global__ __launch_bounds__(128, 4) void sgemm_x2_n64(
    const float* __restrict__ A, const float* __restrict__ B,
    const float* __restrict__ bias, const float* __restrict__ res,
    float* __restrict__ C, int M, int N, int K, int do_relu)
{
    constexpr int BK = 16;

    __shared__ float As[2][BK][64];
    __shared__ float Bs[2][BK][64];

    int tid = threadIdx.x;
    int tx = tid & 7;           // 0..7  -> 8 column groups of 8
    int ty = tid >> 3;          // 0..15 -> 16 row groups of 4
    int bm = blockIdx.y * 64, bn = blockIdx.x * 64;

    int lrow = tid >> 1;            // 0..63
    int lkq  = (tid & 1) * 8;       // 0 or 8
    const float* Ag = A + (size_t)(bm + lrow) * K + lkq;
    const float* Bg = B + (size_t)(bn + lrow) * K + lkq;

    float4 areg[2], breg[2];

    unsigned long long acc[4][4];
    #pragma unroll
    for (int i = 0; i < 4; i++)
        #pragma unroll
        for (int j = 0; j < 4; j++) acc[i][j] = 0ull;

    areg[0] = *(const float4*)(Ag);
    areg[1] = *(const float4*)(Ag + 4);
    breg[0] = *(const float4*)(Bg);
    breg[1] = *(const float4*)(Bg + 4);

    #pragma unroll
    for (int v = 0; v < 2; v++) {
        As[0][lkq + 4*v + 0][lrow] = (&areg[v].x)[0];
        As[0][lkq + 4*v + 1][lrow] = (&areg[v].x)[1];
        As[0][lkq + 4*v + 2][lrow] = (&areg[v].x)[2];
        As[0][lkq + 4*v + 3][lrow] = (&areg[v].x)[3];
        Bs[0][lkq + 4*v + 0][lrow] = (&breg[v].x)[0];
        Bs[0][lkq + 4*v + 1][lrow] = (&breg[v].x)[1];
        Bs[0][lkq + 4*v + 2][lrow] = (&breg[v].x)[2];
        Bs[0][lkq + 4*v + 3][lrow] = (&breg[v].x)[3];
    }
    __syncthreads();

    int nt = K / BK;
    for (int kt = 0; kt < nt; kt++) {
        int cur = kt & 1;
        if (kt + 1 < nt) {
            const float* Ag2 = Ag + (size_t)(kt + 1) * BK;
            const float* Bg2 = Bg + (size_t)(kt + 1) * BK;
            areg[0] = *(const float4*)(Ag2);
            areg[1] = *(const float4*)(Ag2 + 4);
            breg[0] = *(const float4*)(Bg2);
            breg[1] = *(const float4*)(Bg2 + 4);
        }

        #pragma unroll
        for (int kk = 0; kk < BK; kk++) {
            float4 a0 = *(const float4*)&As[cur][kk][4 * ty];
            float4 b0 = *(const float4*)&Bs[cur][kk][8 * tx];
            float4 b1 = *(const float4*)&Bs[cur][kk][8 * tx + 4];

            unsigned long long ap[4], bp[4];
            PACK2F(ap[0], a0.x, a0.x); PACK2F(ap[1], a0.y, a0.y);
            PACK2F(ap[2], a0.z, a0.z); PACK2F(ap[3], a0.w, a0.w);
            PACK2F(bp[0], b0.x, b0.y); PACK2F(bp[1], b0.z, b0.w);
            PACK2F(bp[2], b1.x, b1.y); PACK2F(bp[3], b1.z, b1.w);

            #pragma unroll
            for (int i = 0; i < 4; i++)
                #pragma unroll
                for (int j = 0; j < 4; j++)
                    FMA_F32X2(acc[i][j], ap[i], bp[j], acc[i][j]);
        }

        if (kt + 1 < nt) {
            int nxt = cur ^ 1;
            #pragma unroll
            for (int v = 0; v < 2; v++) {
                As[nxt][lkq + 4*v + 0][lrow] = (&areg[v].x)[0];
                As[nxt][lkq + 4*v + 1][lrow] = (&areg[v].x)[1];
                As[nxt][lkq + 4*v + 2][lrow] = (&areg[v].x)[2];
                As[nxt][lkq + 4*v + 3][lrow] = (&areg[v].x)[3];
                Bs[nxt][lkq + 4*v + 0][lrow] = (&breg[v].x)[0];
                Bs[nxt][lkq + 4*v + 1][lrow] = (&breg[v].x)[1];
                Bs[nxt][lkq + 4*v + 2][lrow] = (&breg[v].x)[2];
                Bs[nxt][lkq + 4*v + 3][lrow] = (&breg[v].x)[3];
            }
            __syncthreads();
        }
    }

    #pragma unroll
    for (int i = 0; i < 4; i++) {
        int r = bm + 4 * ty + i;
        float o[8];
        UNPACK2F(o[0], o[1], acc[i][0]);
        UNPACK2F(o[2], o[3], acc[i][1]);
        UNPACK2F(o[4], o[5], acc[i][2]);
        UNPACK2F(o[6], o[7], acc[i][3]);
        #pragma unroll
        for (int half = 0; half < 2; half++) {
            int c0 = bn + 8 * tx + half * 4;
            float4 v;
            v.x = o[half * 4 + 0]; v.y = o[half * 4 + 1];
            v.z = o[half * 4 + 2]; v.w = o[half * 4 + 3];
            if (bias) {
                v.x += bias[c0 + 0]; v.y += bias[c0 + 1];
                v.z += bias[c0 + 2]; v.w += bias[c0 + 3];
            }
            if (do_relu) {
                v.x = fmaxf(v.x, 0.f); v.y = fmaxf(v.y, 0.f);
                v.z = fmaxf(v.z, 0.f); v.w = fmaxf(v.w, 0.f);
            }
            if (res) {
                float4 rv = *(const float4*)(res + (size_t)r * N + c0);
                v.x += rv.x; v.y += rv.y; v.z += rv.z; v.w += rv.w;
            }
            *(float4*)(C + (size_t)r * N + c0) = v;
        }
    }
}

// ---------------------------------------------------------------------------
// Fused attention (flash-style): per (q-block of 64, b*h)
// ---------------------------------------------------------------------------
#define ATT_SMEM_FLOATS (64*64 + 64*65 + 64*64 + 64*4)

__global__ __launch_bounds__(256) void attn_kernel(
    const float* __restrict__ qkv,          // [B,S,3D]
    const int* __restrict__ relm,           // [B,S,S]
    const unsigned char* __restrict__ mask, // [B,S] (bool)
    const float* __restrict__ relA,         // [3,64]
    float* __restrict__ out)                // [B,S,D]
{
    extern __shared__ float sm[];
    float* QS = sm;                 // 64*64
    float* KP = QS + 64 * 64;       // 64*65 (padded stride 65)
    float* VS = KP + 64 * 65;       // 64*64
    float* RR = VS + 64 * 64;       // 64*4

    int tid = threadIdx.x;
    int tx = tid & 15, ty = tid >> 4;
    int qb = blockIdx.x;            // 0..15
    int bh = blockIdx.y;            // 0..23
    int b = bh / Hc, h = bh % Hc;
    int q0 = qb * 64;

    const float* qbase = qkv + (size_t)(b * Sc) * (3 * Dc) + h * HDc;
    const float* kbase = qbase + Dc;
    const float* vbase = qbase + 2 * Dc;

    {
        int col4 = (tid & 15) * 4;
        for (int r = tid >> 4; r < 64; r += 16) {
            float4 v = *(const float4*)(qbase + (size_t)(q0 + r) * (3 * Dc) + col4);
            *(float4*)&QS[r * 64 + col4] = v;
        }
    }
    __syncthreads();

    if (tid < 192) {
        int q = tid / 3, c = tid % 3;
        float s = 0.f;
        const float* arow = relA + c * HDc;
        #pragma unroll 8
        for (int d = 0; d < 64; d++) s += QS[q * 64 + d] * arow[d];
        RR[q * 4 + c] = s;
    }
    __syncthreads();

    float mrow[4], lrow[4], o[4][4];
    #pragma unroll
    for (int i = 0; i < 4; i++) {
        mrow[i] = -INFINITY; lrow[i] = 0.f;
        #pragma unroll
        for (int j = 0; j < 4; j++) o[i][j] = 0.f;
    }

    const int* rmrow = relm + ((size_t)b * Sc + q0) * Sc;
    const unsigned char* mkrow = mask + (size_t)b * Sc;

    for (int kb = 0; kb < Sc / 64; kb++) {
        int k0 = kb * 64;
        __syncthreads();
        {
            int col4 = (tid & 15) * 4;
            for (int r = tid >> 4; r < 64; r += 16) {
                float4 kv = *(const float4*)(kbase + (size_t)(k0 + r) * (3 * Dc) + col4);
                KP[r * 65 + col4 + 0] = kv.x; KP[r * 65 + col4 + 1] = kv.y;
                KP[r * 65 + col4 + 2] = kv.z; KP[r * 65 + col4 + 3] = kv.w;
                float4 vv = *(const float4*)(vbase + (size_t)(k0 + r) * (3 * Dc) + col4);
                *(float4*)&VS[r * 64 + col4] = vv;
            }
        }
        __syncthreads();

        float s[4][4];
        #pragma unroll
        for (int i = 0; i < 4; i++)
            #pragma unroll
            for (int j = 0; j < 4; j++) s[i][j] = 0.f;
        #pragma unroll 4
        for (int d = 0; d < 64; d++) {
            float a0 = QS[(4 * ty + 0) * 64 + d];
            float a1 = QS[(4 * ty + 1) * 64 + d];
            float a2 = QS[(4 * ty + 2) * 64 + d];
            float a3 = QS[(4 * ty + 3) * 64 + d];
            float b0 = KP[(4 * tx + 0) * 65 + d];
            float b1 = KP[(4 * tx + 1) * 65 + d];
            float b2 = KP[(4 * tx + 2) * 65 + d];
            float b3 = KP[(4 * tx + 3) * 65 + d];
            s[0][0] = fmaf(a0, b0, s[0][0]); s[0][1] = fmaf(a0, b1, s[0][1]);
            s[0][2] = fmaf(a0, b2, s[0][2]); s[0][3] = fmaf(a0, b3, s[0][3]);
            s[1][0] = fmaf(a1, b0, s[1][0]); s[1][1] = fmaf(a1, b1, s[1][1]);
            s[1][2] = fmaf(a1, b2, s[1][2]); s[1][3] = fmaf(a1, b3, s[1][3]);
            s[2][0] = fmaf(a2, b0, s[2][0]); s[2][1] = fmaf(a2, b1, s[2][1]);
            s[2][2] = fmaf(a2, b2, s[2][2]); s[2][3] = fmaf(a2, b3, s[2][3]);
            s[3][0] = fmaf(a3, b0, s[3][0]); s[3][1] = fmaf(a3, b1, s[3][1]);
            s[3][2] = fmaf(a3, b2, s[3][2]); s[3][3] = fmaf(a3, b3, s[3][3]);
        }

        #pragma unroll
        for (int j = 0; j < 4; j++) {
            int kg = k0 + 4 * tx + j;
            unsigned char mk = mkrow[kg];
            #pragma unroll
            for (int i = 0; i < 4; i++) {
                int ql = 4 * ty + i;
                int idx = rmrow[(size_t)ql * Sc + kg] + 1;   // 0,1,2
                float val = (s[i][j] + RR[ql * 4 + idx]) * 0.125f;
                s[i][j] = mk ? -INFINITY : val;
            }
        }

        #pragma unroll
        for (int i = 0; i < 4; i++) {
            float tm = fmaxf(fmaxf(s[i][0], s[i][1]), fmaxf(s[i][2], s[i][3]));
            #pragma unroll
            for (int off = 1; off < 16; off <<= 1)
                tm = fmaxf(tm, __shfl_xor_sync(0xffffffffu, tm, off));
            float nm = fmaxf(mrow[i], tm);
            if (nm == -INFINITY) continue;
            float alpha = (mrow[i] == -INFINITY) ? 0.f : __expf(mrow[i] - nm);
            float rs = 0.f;
            #pragma unroll
            for (int j = 0; j < 4; j++) {
                s[i][j] = __expf(s[i][j] - nm);
                rs += s[i][j];
            }
            #pragma unroll
            for (int off = 1; off < 16; off <<= 1)
                rs += __shfl_xor_sync(0xffffffffu, rs, off);
            lrow[i] = lrow[i] * alpha + rs;
            #pragma unroll
            for (int j = 0; j < 4; j++) o[i][j] *= alpha;
            mrow[i] = nm;
        }

        __syncthreads();
        #pragma unroll
        for (int i = 0; i < 4; i++)
            #pragma unroll
            for (int j = 0; j < 4; j++)
                KP[(4 * ty + i) * 65 + 4 * tx + j] = (mrow[i] == -INFINITY) ? 0.f : s[i][j];
        __syncthreads();

        #pragma unroll 4
        for (int k = 0; k < 64; k++) {
            float4 vv = *(const float4*)&VS[k * 64 + 4 * tx];
            float p0 = KP[(4 * ty + 0) * 65 + k];
            float p1 = KP[(4 * ty + 1) * 65 + k];
            float p2 = KP[(4 * ty + 2) * 65 + k];
            float p3 = KP[(4 * ty + 3) * 65 + k];
            o[0][0] = fmaf(p0, vv.x, o[0][0]); o[0][1] = fmaf(p0, vv.y, o[0][1]);
            o[0][2] = fmaf(p0, vv.z, o[0][2]); o[0][3] = fmaf(p0, vv.w, o[0][3]);
            o[1][0] = fmaf(p1, vv.x, o[1][0]); o[1][1] = fmaf(p1, vv.y, o[1][1]);
            o[1][2] = fmaf(p1, vv.z, o[1][2]); o[1][3] = fmaf(p1, vv.w, o[1][3]);
            o[2][0] = fmaf(p2, vv.x, o[2][0]); o[2][1] = fmaf(p2, vv.y, o[2][1]);
            o[2][2] = fmaf(p2, vv.z, o[2][2]); o[2][3] = fmaf(p2, vv.w, o[2][3]);
            o[3][0] = fmaf(p3, vv.x, o[3][0]); o[3][1] = fmaf(p3, vv.y, o[3][1]);
            o[3][2] = fmaf(p3, vv.z, o[3][2]); o[3][3] = fmaf(p3, vv.w, o[3][3]);
        }
    }

    #pragma unroll
    for (int i = 0; i < 4; i++) {
        float inv = (lrow[i] > 0.f) ? (1.f / lrow[i]) : 0.f;
        int qg = q0 + 4 * ty + i;
        float4 v;
        v.x = o[i][0] * inv; v.y = o[i][1] * inv;
        v.z = o[i][2] * inv; v.w = o[i][3] * inv;
        *(float4*)(out + ((size_t)(b * Sc) + qg) * Dc + h * HDc + 4 * tx) = v;
    }
}

// ---------------------------------------------------------------------------
// Launcher
// ---------------------------------------------------------------------------
extern "C" void kernel_launch(void* const* d_in, const int* in_sizes, int n_in,
                              void* d_out, int out_size)
{
    const float*         inp   = (const float*)d_in[0];
    const unsigned char* mask  = (const unsigned char*)d_in[1];
    const int*           relm  = (const int*)d_in[2];
    const float*         qkv_w = (const float*)d_in[3];
    const float*         relA  = (const float*)d_in[4];
    const float*         o_w   = (const float*)d_in[5];
    const float*         w1    = (const float*)d_in[6];
    const float*         b1    = (const float*)d_in[7];
    const float*         w2    = (const float*)d_in[8];
    const float*         b2    = (const float*)d_in[9];
    const float*         ln1g  = (const float*)d_in[10];
    const float*         ln1b  = (const float*)d_in[11];
    const float*         ln2g  = (const float*)d_in[12];
    const float*         ln2b  = (const float*)d_in[13];
    float* out = (float*)d_out;

    float *p_xln, *p_qkv, *p_att, *p_res1, *p_hln, *p_ff;
    cudaGetSymbolAddress((void**)&p_xln,  g_xln);
    cudaGetSymbolAddress((void**)&p_qkv,  g_qkv);
    cudaGetSymbolAddress((void**)&p_att,  g_att);
    cudaGetSymbolAddress((void**)&p_res1, g_res1);
    cudaGetSymbolAddress((void**)&p_hln,  g_hln);
    cudaGetSymbolAddress((void**)&p_ff,   g_ff);

    cudaFuncSetAttribute(attn_kernel, cudaFuncAttributeMaxDynamicSharedMemorySize,
                         ATT_SMEM_FLOATS * (int)sizeof(float));

    // 1. LN1
    ln_kernel<<<Mrows, 256>>>(inp, ln1g, ln1b, p_xln);

    // 2. QKV = xln @ qkv_w^T  [2048 x 2304], 64x128 tiles, grid 18x32=576
    sgemm_x2<<<dim3(3 * Dc / 128, Mrows / 64), 128>>>(
        p_xln, qkv_w, nullptr, nullptr, p_qkv, Mrows, 3 * Dc, Dc, 0);

    // 3. Fused attention
    attn_kernel<<<dim3(Sc / 64, Bc * Hc), 256, ATT_SMEM_FLOATS * sizeof(float)>>>(
        p_qkv, relm, mask, relA, p_att);

    // 4. res1 = inp + att @ o_w^T  [2048 x 768], 64x64 tiles, grid 12x32=384
    sgemm_x2_n64<<<dim3(Dc / 64, Mrows / 64), 128>>>(
        p_att, o_w, nullptr, inp, p_res1, Mrows, Dc, Dc, 0);

    // 5. LN2
    ln_kernel<<<Mrows, 256>>>(p_res1, ln2g, ln2b, p_hln);

    // 6. ff = relu(hln @ w1^T + b1)  [2048 x 3072], 64x128 tiles, grid 24x32=768
    sgemm_x2<<<dim3(DFFc / 128, Mrows / 64), 128>>>(
        p_hln, w1, b1, nullptr, p_ff, Mrows, DFFc, Dc, 1);

    // 7. out = res1 + ff @ w2^T + b2  [2048 x 768], 64x64 tiles, grid 12x32=384
    sgemm_x2_n64<<<dim3(Dc / 64, Mrows / 64), 128>>>(
        p_ff, w2, b2, p_res1, out, Mrows, Dc, DFFc, 0);
}

// round 16
// speedup vs baseline: 1.7784x; 1.2517x over previous
#include <cuda_runtime.h>
#include <math.h>

// Problem dimensions
#define Bc   2
#define Sc   1024
#define Dc   768
#define Hc   12
#define HDc  64
#define DFFc 3072
#define Mrows (Bc*Sc)          // 2048

// Packed f32x2 helpers (FFMA2 path — PTX-only)
#define FMA_F32X2(d, a, b, c) \
    asm("fma.rn.f32x2 %0, %1, %2, %3;" : "=l"(d) : "l"(a), "l"(b), "l"(c))
#define PACK2F(out, lo, hi) \
    asm("mov.b64 %0, {%1, %2};" : "=l"(out) : "f"(lo), "f"(hi))
#define UNPACK2F(lo, hi, in) \
    asm("mov.b64 {%0, %1}, %2;" : "=f"(lo), "=f"(hi) : "l"(in))

// ---------------------------------------------------------------------------
// Scratch (allocation-free: __device__ globals)
// ---------------------------------------------------------------------------
__device__ float g_xln [Mrows*Dc];
__device__ float g_qkv [Mrows*3*Dc];
__device__ float g_att [Mrows*Dc];
__device__ float g_res1[Mrows*Dc];
__device__ float g_hln [Mrows*Dc];
__device__ float g_ff  [Mrows*DFFc];
__device__ float g_part[2*Mrows*Dc];   // split-K partials (2 slices x 2048 x 768)

// ---------------------------------------------------------------------------
// LayerNorm: one block per row of 768
// ---------------------------------------------------------------------------
__global__ __launch_bounds__(256) void ln_kernel(
    const float* __restrict__ x, const float* __restrict__ g,
    const float* __restrict__ b, float* __restrict__ y)
{
    __shared__ float red[16];
    int row = blockIdx.x;
    int t = threadIdx.x;
    const float* xr = x + (size_t)row * Dc;
    float v0 = xr[t], v1 = xr[t + 256], v2 = xr[t + 512];
    float s  = v0 + v1 + v2;
    float ss = v0*v0 + v1*v1 + v2*v2;
    #pragma unroll
    for (int o = 16; o > 0; o >>= 1) {
        s  += __shfl_xor_sync(0xffffffffu, s,  o);
        ss += __shfl_xor_sync(0xffffffffu, ss, o);
    }
    int w = t >> 5;
    if ((t & 31) == 0) { red[w] = s; red[8 + w] = ss; }
    __syncthreads();
    s = 0.f; ss = 0.f;
    #pragma unroll
    for (int i = 0; i < 8; i++) { s += red[i]; ss += red[8 + i]; }
    float mean = s * (1.0f / Dc);
    float var  = ss * (1.0f / Dc) - mean * mean;
    float inv  = rsqrtf(var + 1e-5f);
    float* yr = y + (size_t)row * Dc;
    yr[t]       = (v0 - mean) * inv * g[t]       + b[t];
    yr[t + 256] = (v1 - mean) * inv * g[t + 256] + b[t + 256];
    yr[t + 512] = (v2 - mean) * inv * g[t + 512] + b[t + 512];
}

// ---------------------------------------------------------------------------
// SGEMM engine (R10): tile 64x128, BK=16, 128 threads, 8x8/thread, FFMA2.
// Fused epilogue variant — for QKV (576 CTAs) and MLP1 (768 CTAs).
// ---------------------------------------------------------------------------
__global__ __launch_bounds__(128, 4) void sgemm_x2(
    const float* __restrict__ A, const float* __restrict__ B,
    const float* __restrict__ bias, const float* __restrict__ res,
    float* __restrict__ C, int M, int N, int K, int do_relu)
{
    constexpr int BK = 16;

    __shared__ float As[2][BK][64];
    __shared__ float Bs[2][BK][128];

    int tid = threadIdx.x;
    int tx = tid & 15;
    int ty = tid >> 4;
    int bm = blockIdx.y * 64, bn = blockIdx.x * 128;

    int arow = tid >> 1;
    int akq  = (tid & 1) * 8;
    const float* Ag = A + (size_t)(bm + arow) * K + akq;
    const float* Bg = B + (size_t)(bn + tid) * K;

    float4 areg[2], breg[4];

    unsigned long long acc[8][4];
    #pragma unroll
    for (int i = 0; i < 8; i++)
        #pragma unroll
        for (int j = 0; j < 4; j++) acc[i][j] = 0ull;

    areg[0] = *(const float4*)(Ag);
    areg[1] = *(const float4*)(Ag + 4);
    #pragma unroll
    for (int v = 0; v < 4; v++) breg[v] = *(const float4*)(Bg + 4 * v);

    #pragma unroll
    for (int v = 0; v < 2; v++) {
        As[0][akq + 4*v + 0][arow] = (&areg[v].x)[0];
        As[0][akq + 4*v + 1][arow] = (&areg[v].x)[1];
        As[0][akq + 4*v + 2][arow] = (&areg[v].x)[2];
        As[0][akq + 4*v + 3][arow] = (&areg[v].x)[3];
    }
    #pragma unroll
    for (int v = 0; v < 4; v++) {
        Bs[0][4*v + 0][tid] = breg[v].x;
        Bs[0][4*v + 1][tid] = breg[v].y;
        Bs[0][4*v + 2][tid] = breg[v].z;
        Bs[0][4*v + 3][tid] = breg[v].w;
    }
    __syncthreads();

    int nt = K / BK;
    for (int kt = 0; kt < nt; kt++) {
        int cur = kt & 1;
        if (kt + 1 < nt) {
            const float* Ag2 = Ag + (size_t)(kt + 1) * BK;
            const float* Bg2 = Bg + (size_t)(kt + 1) * BK;
            areg[0] = *(const float4*)(Ag2);
            areg[1] = *(const float4*)(Ag2 + 4);
            #pragma unroll
            for (int v = 0; v < 4; v++) breg[v] = *(const float4*)(Bg2 + 4 * v);
        }

        #pragma unroll
        for (int kk = 0; kk < BK; kk++) {
            float4 a0 = *(const float4*)&As[cur][kk][8 * ty];
            float4 a1 = *(const float4*)&As[cur][kk][8 * ty + 4];
            float4 b0 = *(const float4*)&Bs[cur][kk][4 * tx];
            float4 b1 = *(const float4*)&Bs[cur][kk][64 + 4 * tx];

            unsigned long long ap[8], bp[4];
            PACK2F(ap[0], a0.x, a0.x); PACK2F(ap[1], a0.y, a0.y);
            PACK2F(ap[2], a0.z, a0.z); PACK2F(ap[3], a0.w, a0.w);
            PACK2F(ap[4], a1.x, a1.x); PACK2F(ap[5], a1.y, a1.y);
            PACK2F(ap[6], a1.z, a1.z); PACK2F(ap[7], a1.w, a1.w);
            PACK2F(bp[0], b0.x, b0.y); PACK2F(bp[1], b0.z, b0.w);
            PACK2F(bp[2], b1.x, b1.y); PACK2F(bp[3], b1.z, b1.w);

            #pragma unroll
            for (int i = 0; i < 8; i++)
                #pragma unroll
                for (int j = 0; j < 4; j++)
                    FMA_F32X2(acc[i][j], ap[i], bp[j], acc[i][j]);
        }

        if (kt + 1 < nt) {
            int nxt = cur ^ 1;
            #pragma unroll
            for (int v = 0; v < 2; v++) {
                As[nxt][akq + 4*v + 0][arow] = (&areg[v].x)[0];
                As[nxt][akq + 4*v + 1][arow] = (&areg[v].x)[1];
                As[nxt][akq + 4*v + 2][arow] = (&areg[v].x)[2];
                As[nxt][akq + 4*v + 3][arow] = (&areg[v].x)[3];
            }
            #pragma unroll
            for (int v = 0; v < 4; v++) {
                Bs[nxt][4*v + 0][tid] = breg[v].x;
                Bs[nxt][4*v + 1][tid] = breg[v].y;
                Bs[nxt][4*v + 2][tid] = breg[v].z;
                Bs[nxt][4*v + 3][tid] = breg[v].w;
            }
            __syncthreads();
        }
    }

    #pragma unroll
    for (int i = 0; i < 8; i++) {
        int r = bm + 8 * ty + i;
        float o[8];
        UNPACK2F(o[0], o[1], acc[i][0]);
        UNPACK2F(o[2], o[3], acc[i][1]);
        UNPACK2F(o[4], o[5], acc[i][2]);
        UNPACK2F(o[6], o[7], acc[i][3]);
        #pragma unroll
        for (int half = 0; half < 2; half++) {
            int c0 = bn + half * 64 + 4 * tx;
            float4 v;
            v.x = o[half * 4 + 0]; v.y = o[half * 4 + 1];
            v.z = o[half * 4 + 2]; v.w = o[half * 4 + 3];
            if (bias) {
                v.x += bias[c0 + 0]; v.y += bias[c0 + 1];
                v.z += bias[c0 + 2]; v.w += bias[c0 + 3];
            }
            if (do_relu) {
                v.x = fmaxf(v.x, 0.f); v.y = fmaxf(v.y, 0.f);
                v.z = fmaxf(v.z, 0.f); v.w = fmaxf(v.w, 0.f);
            }
            if (res) {
                float4 rv = *(const float4*)(res + (size_t)r * N + c0);
                v.x += rv.x; v.y += rv.y; v.z += rv.z; v.w += rv.w;
            }
            *(float4*)(C + (size_t)r * N + c0) = v;
        }
    }
}

// ---------------------------------------------------------------------------
// Split-K variant of the SAME engine: blockIdx.z = K-slice, raw partial out.
// For N=768 GEMMs (O-proj, MLP2): grid (6,32,2)=384 CTAs.
// ---------------------------------------------------------------------------
__global__ __launch_bounds__(128, 4) void sgemm_x2_sk(
    const float* __restrict__ A, const float* __restrict__ B,
    float* __restrict__ Cpart, int M, int N, int K, int Ksl)
{
    constexpr int BK = 16;

    __shared__ float As[2][BK][64];
    __shared__ float Bs[2][BK][128];

    int tid = threadIdx.x;
    int tx = tid & 15;
    int ty = tid >> 4;
    int bm = blockIdx.y * 64, bn = blockIdx.x * 128;
    int kbase = blockIdx.z * Ksl;
    float* Cout = Cpart + (size_t)blockIdx.z * M * N;

    int arow = tid >> 1;
    int akq  = (tid & 1) * 8;
    const float* Ag = A + (size_t)(bm + arow) * K + kbase + akq;
    const float* Bg = B + (size_t)(bn + tid) * K + kbase;

    float4 areg[2], breg[4];

    unsigned long long acc[8][4];
    #pragma unroll
    for (int i = 0; i < 8; i++)
        #pragma unroll
        for (int j = 0; j < 4; j++) acc[i][j] = 0ull;

    areg[0] = *(const float4*)(Ag);
    areg[1] = *(const float4*)(Ag + 4);
    #pragma unroll
    for (int v = 0; v < 4; v++) breg[v] = *(const float4*)(Bg + 4 * v);

    #pragma unroll
    for (int v = 0; v < 2; v++) {
        As[0][akq + 4*v + 0][arow] = (&areg[v].x)[0];
        As[0][akq + 4*v + 1][arow] = (&areg[v].x)[1];
        As[0][akq + 4*v + 2][arow] = (&areg[v].x)[2];
        As[0][akq + 4*v + 3][arow] = (&areg[v].x)[3];
    }
    #pragma unroll
    for (int v = 0; v < 4; v++) {
        Bs[0][4*v + 0][tid] = breg[v].x;
        Bs[0][4*v + 1][tid] = breg[v].y;
        Bs[0][4*v + 2][tid] = breg[v].z;
        Bs[0][4*v + 3][tid] = breg[v].w;
    }
    __syncthreads();

    int nt = Ksl / BK;
    for (int kt = 0; kt < nt; kt++) {
        int cur = kt & 1;
        if (kt + 1 < nt) {
            const float* Ag2 = Ag + (size_t)(kt + 1) * BK;
            const float* Bg2 = Bg + (size_t)(kt + 1) * BK;
            areg[0] = *(const float4*)(Ag2);
            areg[1] = *(const float4*)(Ag2 + 4);
            #pragma unroll
            for (int v = 0; v < 4; v++) breg[v] = *(const float4*)(Bg2 + 4 * v);
        }

        #pragma unroll
        for (int kk = 0; kk < BK; kk++) {
            float4 a0 = *(const float4*)&As[cur][kk][8 * ty];
            float4 a1 = *(const float4*)&As[cur][kk][8 * ty + 4];
            float4 b0 = *(const float4*)&Bs[cur][kk][4 * tx];
            float4 b1 = *(const float4*)&Bs[cur][kk][64 + 4 * tx];

            unsigned long long ap[8], bp[4];
            PACK2F(ap[0], a0.x, a0.x); PACK2F(ap[1], a0.y, a0.y);
            PACK2F(ap[2], a0.z, a0.z); PACK2F(ap[3], a0.w, a0.w);
            PACK2F(ap[4], a1.x, a1.x); PACK2F(ap[5], a1.y, a1.y);
            PACK2F(ap[6], a1.z, a1.z); PACK2F(ap[7], a1.w, a1.w);
            PACK2F(bp[0], b0.x, b0.y); PACK2F(bp[1], b0.z, b0.w);
            PACK2F(bp[2], b1.x, b1.y); PACK2F(bp[3], b1.z, b1.w);

            #pragma unroll
            for (int i = 0; i < 8; i++)
                #pragma unroll
                for (int j = 0; j < 4; j++)
                    FMA_F32X2(acc[i][j], ap[i], bp[j], acc[i][j]);
        }

        if (kt + 1 < nt) {
            int nxt = cur ^ 1;
            #pragma unroll
            for (int v = 0; v < 2; v++) {
                As[nxt][akq + 4*v + 0][arow] = (&areg[v].x)[0];
                As[nxt][akq + 4*v + 1][arow] = (&areg[v].x)[1];
                As[nxt][akq + 4*v + 2][arow] = (&areg[v].x)[2];
                As[nxt][akq + 4*v + 3][arow] = (&areg[v].x)[3];
            }
            #pragma unroll
            for (int v = 0; v < 4; v++) {
                Bs[nxt][4*v + 0][tid] = breg[v].x;
                Bs[nxt][4*v + 1][tid] = breg[v].y;
                Bs[nxt][4*v + 2][tid] = breg[v].z;
                Bs[nxt][4*v + 3][tid] = breg[v].w;
            }
            __syncthreads();
        }
    }

    #pragma unroll
    for (int i = 0; i < 8; i++) {
        int r = bm + 8 * ty + i;
        float o[8];
        UNPACK2F(o[0], o[1], acc[i][0]);
        UNPACK2F(o[2], o[3], acc[i][1]);
        UNPACK2F(o[4], o[5], acc[i][2]);
        UNPACK2F(o[6], o[7], acc[i][3]);
        #pragma unroll
        for (int half = 0; half < 2; half++) {
            int c0 = bn + half * 64 + 4 * tx;
            float4 v;
            v.x = o[half * 4 + 0]; v.y = o[half * 4 + 1];
            v.z = o[half * 4 + 2]; v.w = o[half * 4 + 3];
            *(float4*)(Cout + (size_t)r * N + c0) = v;
        }
    }
}

// ---------------------------------------------------------------------------
// Split-K reduce: C = p0 + p1 (+bias) (+res), float4-vectorized.
// ---------------------------------------------------------------------------
__global__ __launch_bounds__(256) void reduce2_kernel(
    const float* __restrict__ p0, const float* __restrict__ p1,
    const float* __restrict__ bias, const float* __restrict__ res,
    float* __restrict__ C, int N, int total4)
{
    int i = blockIdx.x * blockDim.x + threadIdx.x;
    if (i >= total4) return;
    float4 a = ((const float4*)p0)[i];
    float4 b = ((const float4*)p1)[i];
    float4 v;
    v.x = a.x + b.x; v.y = a.y + b.y; v.z = a.z + b.z; v.w = a.w + b.w;
    if (bias) {
        int c0 = (i * 4) % N;
        v.x += bias[c0 + 0]; v.y += bias[c0 + 1];
        v.z += bias[c0 + 2]; v.w += bias[c0 + 3];
    }
    if (res) {
        float4 rv = ((const float4*)res)[i];
        v.x += rv.x; v.y += rv.y; v.z += rv.z; v.w += rv.w;
    }
    ((float4*)C)[i] = v;
}

// ---------------------------------------------------------------------------
// Fused attention (flash-style): per (q-block of 64, b*h)
// ---------------------------------------------------------------------------
#define ATT_SMEM_FLOATS (64*64 + 64*65 + 64*64 + 64*4)

__global__ __launch_bounds__(256) void attn_kernel(
    const float* __restrict__ qkv,          // [B,S,3D]
    const int* __restrict__ relm,           // [B,S,S]
    const unsigned char* __restrict__ mask, // [B,S] (bool)
    const float* __restrict__ relA,         // [3,64]
    float* __restrict__ out)                // [B,S,D]
{
    extern __shared__ float sm[];
    float* QS = sm;
    float* KP = QS + 64 * 64;
    float* VS = KP + 64 * 65;
    float* RR = VS + 64 * 64;

    int tid = threadIdx.x;
    int tx = tid & 15, ty = tid >> 4;
    int qb = blockIdx.x;
    int bh = blockIdx.y;
    int b = bh / Hc, h = bh % Hc;
    int q0 = qb * 64;

    const float* qbase = qkv + (size_t)(b * Sc) * (3 * Dc) + h * HDc;
    const float* kbase = qbase + Dc;
    const float* vbase = qbase + 2 * Dc;

    {
        int col4 = (tid & 15) * 4;
        for (int r = tid >> 4; r < 64; r += 16) {
            float4 v = *(const float4*)(qbase + (size_t)(q0 + r) * (3 * Dc) + col4);
            *(float4*)&QS[r * 64 + col4] = v;
        }
    }
    __syncthreads();

    if (tid < 192) {
        int q = tid / 3, c = tid % 3;
        float s = 0.f;
        const float* arow = relA + c * HDc;
        #pragma unroll 8
        for (int d = 0; d < 64; d++) s += QS[q * 64 + d] * arow[d];
        RR[q * 4 + c] = s;
    }
    __syncthreads();

    float mrow[4], lrow[4], o[4][4];
    #pragma unroll
    for (int i = 0; i < 4; i++) {
        mrow[i] = -INFINITY; lrow[i] = 0.f;
        #pragma unroll
        for (int j = 0; j < 4; j++) o[i][j] = 0.f;
    }

    const int* rmrow = relm + ((size_t)b * Sc + q0) * Sc;
    const unsigned char* mkrow = mask + (size_t)b * Sc;

    for (int kb = 0; kb < Sc / 64; kb++) {
        int k0 = kb * 64;
        __syncthreads();
        {
            int col4 = (tid & 15) * 4;
            for (int r = tid >> 4; r < 64; r += 16) {
                float4 kv = *(const float4*)(kbase + (size_t)(k0 + r) * (3 * Dc) + col4);
                KP[r * 65 + col4 + 0] = kv.x; KP[r * 65 + col4 + 1] = kv.y;
                KP[r * 65 + col4 + 2] = kv.z; KP[r * 65 + col4 + 3] = kv.w;
                float4 vv = *(const float4*)(vbase + (size_t)(k0 + r) * (3 * Dc) + col4);
                *(float4*)&VS[r * 64 + col4] = vv;
            }
        }
        __syncthreads();

        float s[4][4];
        #pragma unroll
        for (int i = 0; i < 4; i++)
            #pragma unroll
            for (int j = 0; j < 4; j++) s[i][j] = 0.f;
        #pragma unroll 4
        for (int d = 0; d < 64; d++) {
            float a0 = QS[(4 * ty + 0) * 64 + d];
            float a1 = QS[(4 * ty + 1) * 64 + d];
            float a2 = QS[(4 * ty + 2) * 64 + d];
            float a3 = QS[(4 * ty + 3) * 64 + d];
            float b0 = KP[(4 * tx + 0) * 65 + d];
            float b1 = KP[(4 * tx + 1) * 65 + d];
            float b2 = KP[(4 * tx + 2) * 65 + d];
            float b3 = KP[(4 * tx + 3) * 65 + d];
            s[0][0] = fmaf(a0, b0, s[0][0]); s[0][1] = fmaf(a0, b1, s[0][1]);
            s[0][2] = fmaf(a0, b2, s[0][2]); s[0][3] = fmaf(a0, b3, s[0][3]);
            s[1][0] = fmaf(a1, b0, s[1][0]); s[1][1] = fmaf(a1, b1, s[1][1]);
            s[1][2] = fmaf(a1, b2, s[1][2]); s[1][3] = fmaf(a1, b3, s[1][3]);
            s[2][0] = fmaf(a2, b0, s[2][0]); s[2][1] = fmaf(a2, b1, s[2][1]);
            s[2][2] = fmaf(a2, b2, s[2][2]); s[2][3] = fmaf(a2, b3, s[2][3]);
            s[3][0] = fmaf(a3, b0, s[3][0]); s[3][1] = fmaf(a3, b1, s[3][1]);
            s[3][2] = fmaf(a3, b2, s[3][2]); s[3][3] = fmaf(a3, b3, s[3][3]);
        }

        #pragma unroll
        for (int j = 0; j < 4; j++) {
            int kg = k0 + 4 * tx + j;
            unsigned char mk = mkrow[kg];
            #pragma unroll
            for (int i = 0; i < 4; i++) {
                int ql = 4 * ty + i;
                int idx = rmrow[(size_t)ql * Sc + kg] + 1;   // 0,1,2
                float val = (s[i][j] + RR[ql * 4 + idx]) * 0.125f;
                s[i][j] = mk ? -INFINITY : val;
            }
        }

        #pragma unroll
        for (int i = 0; i < 4; i++) {
            float tm = fmaxf(fmaxf(s[i][0], s[i][1]), fmaxf(s[i][2], s[i][3]));
            #pragma unroll
            for (int off = 1; off < 16; off <<= 1)
                tm = fmaxf(tm, __shfl_xor_sync(0xffffffffu, tm, off));
            float nm = fmaxf(mrow[i], tm);
            if (nm == -INFINITY) continue;
            float alpha = (mrow[i] == -INFINITY) ? 0.f : __expf(mrow[i] - nm);
            float rs = 0.f;
            #pragma unroll
            for (int j = 0; j < 4; j++) {
                s[i][j] = __expf(s[i][j] - nm);
                rs += s[i][j];
            }
            #pragma unroll
            for (int off = 1; off < 16; off <<= 1)
                rs += __shfl_xor_sync(0xffffffffu, rs, off);
            lrow[i] = lrow[i] * alpha + rs;
            #pragma unroll
            for (int j = 0; j < 4; j++) o[i][j] *= alpha;
            mrow[i] = nm;
        }

        __syncthreads();
        #pragma unroll
        for (int i = 0; i < 4; i++)
            #pragma unroll
            for (int j = 0; j < 4; j++)
                KP[(4 * ty + i) * 65 + 4 * tx + j] = (mrow[i] == -INFINITY) ? 0.f : s[i][j];
        __syncthreads();

        #pragma unroll 4
        for (int k = 0; k < 64; k++) {
            float4 vv = *(const float4*)&VS[k * 64 + 4 * tx];
            float p0 = KP[(4 * ty + 0) * 65 + k];
            float p1 = KP[(4 * ty + 1) * 65 + k];
            float p2 = KP[(4 * ty + 2) * 65 + k];
            float p3 = KP[(4 * ty + 3) * 65 + k];
            o[0][0] = fmaf(p0, vv.x, o[0][0]); o[0][1] = fmaf(p0, vv.y, o[0][1]);
            o[0][2] = fmaf(p0, vv.z, o[0][2]); o[0][3] = fmaf(p0, vv.w, o[0][3]);
            o[1][0] = fmaf(p1, vv.x, o[1][0]); o[1][1] = fmaf(p1, vv.y, o[1][1]);
            o[1][2] = fmaf(p1, vv.z, o[1][2]); o[1][3] = fmaf(p1, vv.w, o[1][3]);
            o[2][0] = fmaf(p2, vv.x, o[2][0]); o[2][1] = fmaf(p2, vv.y, o[2][1]);
            o[2][2] = fmaf(p2, vv.z, o[2][2]); o[2][3] = fmaf(p2, vv.w, o[2][3]);
            o[3][0] = fmaf(p3, vv.x, o[3][0]); o[3][1] = fmaf(p3, vv.y, o[3][1]);
            o[3][2] = fmaf(p3, vv.z, o[3][2]); o[3][3] = fmaf(p3, vv.w, o[3][3]);
        }
    }

    #pragma unroll
    for (int i = 0; i < 4; i++) {
        float inv = (lrow[i] > 0.f) ? (1.f / lrow[i]) : 0.f;
        int qg = q0 + 4 * ty + i;
        float4 v;
        v.x = o[i][0] * inv; v.y = o[i][1] * inv;
        v.z = o[i][2] * inv; v.w = o[i][3] * inv;
        *(float4*)(out + ((size_t)(b * Sc) + qg) * Dc + h * HDc + 4 * tx) = v;
    }
}

// ---------------------------------------------------------------------------
// Launcher
// ---------------------------------------------------------------------------
extern "C" void kernel_launch(void* const* d_in, const int* in_sizes, int n_in,
                              void* d_out, int out_size)
{
    const float*         inp   = (const float*)d_in[0];
    const unsigned char* mask  = (const unsigned char*)d_in[1];
    const int*           relm  = (const int*)d_in[2];
    const float*         qkv_w = (const float*)d_in[3];
    const float*         relA  = (const float*)d_in[4];
    const float*         o_w   = (const float*)d_in[5];
    const float*         w1    = (const float*)d_in[6];
    const float*         b1    = (const float*)d_in[7];
    const float*         w2    = (const float*)d_in[8];
    const float*         b2    = (const float*)d_in[9];
    const float*         ln1g  = (const float*)d_in[10];
    const float*         ln1b  = (const float*)d_in[11];
    const float*         ln2g  = (const float*)d_in[12];
    const float*         ln2b  = (const float*)d_in[13];
    float* out = (float*)d_out;

    float *p_xln, *p_qkv, *p_att, *p_res1, *p_hln, *p_ff, *p_part;
    cudaGetSymbolAddress((void**)&p_xln,  g_xln);
    cudaGetSymbolAddress((void**)&p_qkv,  g_qkv);
    cudaGetSymbolAddress((void**)&p_att,  g_att);
    cudaGetSymbolAddress((void**)&p_res1, g_res1);
    cudaGetSymbolAddress((void**)&p_hln,  g_hln);
    cudaGetSymbolAddress((void**)&p_ff,   g_ff);
    cudaGetSymbolAddress((void**)&p_part, g_part);

    cudaFuncSetAttribute(attn_kernel, cudaFuncAttributeMaxDynamicSharedMemorySize,
                         ATT_SMEM_FLOATS * (int)sizeof(float));

    const int total4 = Mrows * Dc / 4;   // 393216 float4s
    const int redGrid = (total4 + 255) / 256;

    // 1. LN1
    ln_kernel<<<Mrows, 256>>>(inp, ln1g, ln1b, p_xln);

    // 2. QKV = xln @ qkv_w^T  [2048 x 2304], grid 18x32=576
    sgemm_x2<<<dim3(3 * Dc / 128, Mrows / 64), 128>>>(
        p_xln, qkv_w, nullptr, nullptr, p_qkv, Mrows, 3 * Dc, Dc, 0);

    // 3. Fused attention
    attn_kernel<<<dim3(Sc / 64, Bc * Hc), 256, ATT_SMEM_FLOATS * sizeof(float)>>>(
        p_qkv, relm, mask, relA, p_att);

    // 4. res1 = inp + att @ o_w^T  [2048 x 768], split-K=2, grid (6,32,2)=384
    sgemm_x2_sk<<<dim3(Dc / 128, Mrows / 64, 2), 128>>>(
        p_att, o_w, p_part, Mrows, Dc, Dc, Dc / 2);
    reduce2_kernel<<<redGrid, 256>>>(
        p_part, p_part + (size_t)Mrows * Dc, nullptr, inp, p_res1, Dc, total4);

    // 5. LN2
    ln_kernel<<<Mrows, 256>>>(p_res1, ln2g, ln2b, p_hln);

    // 6. ff = relu(hln @ w1^T + b1)  [2048 x 3072], grid 24x32=768
    sgemm_x2<<<dim3(DFFc / 128, Mrows / 64), 128>>>(
        p_hln, w1, b1, nullptr, p_ff, Mrows, DFFc, Dc, 1);

    // 7. out = res1 + ff @ w2^T + b2  [2048 x 768], split-K=2, grid (6,32,2)=384
    sgemm_x2_sk<<<dim3(Dc / 128, Mrows / 64, 2), 128>>>(
        p_ff, w2, p_part, Mrows, Dc, DFFc, DFFc / 2);
    reduce2_kernel<<<redGrid, 256>>>(
        p_part, p_part + (size_t)Mrows * Dc, b2, p_res1, out, Dc, total4);
}